// round 2
// baseline (speedup 1.0000x reference)
#include <cuda_runtime.h>
#include <cstdint>

// Problem constants
#define T_TOK 8192      // B*S tokens
#define D_DIM 1024
#define F_DIM 4096
#define E_NUM 8

// GEMM tiling
#define BM 128
#define BN 64
#define BK 32
#define APAD 8
#define BPAD 8

// ---------------- scratch (device globals; no allocations) ----------------
__device__ float g_h[(size_t)2 * T_TOK * F_DIM];   // per-(token,slot) hidden: 256 MB
__device__ float g_o[(size_t)2 * T_TOK * D_DIM];   // per-(token,slot) output: 64 MB
__device__ int   g_entries[E_NUM * T_TOK];         // per-expert token-slot lists
__device__ int   g_cnt[E_NUM];
__device__ float g_w[2 * T_TOK];                   // routing weights per (token,slot)

// ---------------- helpers ----------------
__device__ __forceinline__ float tf32r(float x) {
    uint32_t u;
    asm("cvt.rna.tf32.f32 %0, %1;" : "=r"(u) : "f"(x));
    return __uint_as_float(u);
}

__device__ __forceinline__ void mma8(float c[4], const uint32_t a[4], const uint32_t b[2]) {
    asm volatile(
        "mma.sync.aligned.m16n8k8.row.col.f32.tf32.tf32.f32 "
        "{%0,%1,%2,%3}, {%4,%5,%6,%7}, {%8,%9}, {%0,%1,%2,%3};"
        : "+f"(c[0]), "+f"(c[1]), "+f"(c[2]), "+f"(c[3])
        : "r"(a[0]), "r"(a[1]), "r"(a[2]), "r"(a[3]), "r"(b[0]), "r"(b[1]));
}

// ---------------- kernel 0: zero expert counters ----------------
__global__ void zero_cnt_kernel() {
    if (threadIdx.x < E_NUM) g_cnt[threadIdx.x] = 0;
}

// ---------------- kernel 1: router (warp per token) ----------------
__global__ void router_kernel(const float* __restrict__ x, const float* __restrict__ gw) {
    int warp = (blockIdx.x * blockDim.x + threadIdx.x) >> 5;
    int lane = threadIdx.x & 31;
    if (warp >= T_TOK) return;
    const float* xr = x + (size_t)warp * D_DIM;

    float acc[E_NUM];
#pragma unroll
    for (int e = 0; e < E_NUM; e++) acc[e] = 0.f;

    for (int j = lane; j < D_DIM; j += 32) {
        float xv = xr[j];
        const float4* gp = (const float4*)(gw + (size_t)j * E_NUM);
        float4 g0 = gp[0], g1 = gp[1];
        acc[0] += xv * g0.x; acc[1] += xv * g0.y; acc[2] += xv * g0.z; acc[3] += xv * g0.w;
        acc[4] += xv * g1.x; acc[5] += xv * g1.y; acc[6] += xv * g1.z; acc[7] += xv * g1.w;
    }
#pragma unroll
    for (int e = 0; e < E_NUM; e++) {
#pragma unroll
        for (int o = 16; o > 0; o >>= 1)
            acc[e] += __shfl_down_sync(0xffffffffu, acc[e], o);
    }
    if (lane == 0) {
        float v0 = -1e30f, v1 = -1e30f;
        int e0 = 0, e1 = 0;
        for (int e = 0; e < E_NUM; e++) {
            float v = acc[e];
            if (v > v0)      { v1 = v0; e1 = e0; v0 = v; e0 = e; }
            else if (v > v1) { v1 = v;  e1 = e; }
        }
        float ex = expf(v1 - v0);
        float s  = 1.f / (1.f + ex);
        g_w[warp * 2 + 0] = s;
        g_w[warp * 2 + 1] = ex * s;
        int p0 = atomicAdd(&g_cnt[e0], 1);
        g_entries[e0 * T_TOK + p0] = warp * 2 + 0;
        int p1 = atomicAdd(&g_cnt[e1], 1);
        g_entries[e1 * T_TOK + p1] = warp * 2 + 1;
    }
}

// ---------------- kernel 2: grouped up-projection (dual-B, silu-gated) ----------------
// h[entry, f] = silu(x[tok] @ wi0[e]) * (x[tok] @ wi1[e])
__global__ __launch_bounds__(256) void ffn_up_kernel(
    const float* __restrict__ x,
    const float* __restrict__ wi0,
    const float* __restrict__ wi1)
{
    int e = blockIdx.z;
    int mtile = blockIdx.y;
    int ntile = blockIdx.x;
    int nt = g_cnt[e];
    if (mtile * BM >= nt) return;

    __shared__ float As[BK][BM + APAD];
    __shared__ float Bs0[BK][BN + BPAD];
    __shared__ float Bs1[BK][BN + BPAD];
    __shared__ int s_entry[BM];
    __shared__ int s_tok[BM];

    int tid = threadIdx.x;
    if (tid < BM) {
        int i = mtile * BM + tid;
        if (i < nt) {
            int ent = g_entries[e * T_TOK + i];
            s_entry[tid] = ent;
            s_tok[tid] = ent >> 1;
        } else {
            s_entry[tid] = -1;
            s_tok[tid] = 0;
        }
    }
    __syncthreads();

    float c0[2][4][4], c1[2][4][4];
#pragma unroll
    for (int i = 0; i < 2; i++)
#pragma unroll
        for (int j = 0; j < 4; j++)
#pragma unroll
            for (int k = 0; k < 4; k++) { c0[i][j][k] = 0.f; c1[i][j][k] = 0.f; }

    // A-load mapping: 2 threads per row, 16 consecutive k each
    int lrow = tid >> 1;
    int lk   = (tid & 1) * 16;
    const float* aptr = x + (size_t)s_tok[lrow] * D_DIM + lk;
    // B-load mapping: 8 threads per k-row, 8 consecutive n each
    int bkrow = tid >> 3;
    int bcol  = (tid & 7) * 8;
    const float* b0p = wi0 + ((size_t)e * D_DIM + bkrow) * F_DIM + (size_t)ntile * BN + bcol;
    const float* b1p = wi1 + ((size_t)e * D_DIM + bkrow) * F_DIM + (size_t)ntile * BN + bcol;

    int lane = tid & 31, warp = tid >> 5;
    int g = lane >> 2, t4 = lane & 3;
    int wm = warp >> 1, wn = warp & 1;
    int mbase = wm * 32, nbase = wn * 32;

    for (int kt = 0; kt < D_DIM; kt += BK) {
#pragma unroll
        for (int q = 0; q < 4; q++) {
            float4 v = *(const float4*)(aptr + kt + q * 4);
            As[lk + q * 4 + 0][lrow] = tf32r(v.x);
            As[lk + q * 4 + 1][lrow] = tf32r(v.y);
            As[lk + q * 4 + 2][lrow] = tf32r(v.z);
            As[lk + q * 4 + 3][lrow] = tf32r(v.w);
        }
        {
            const float* p0 = b0p + (size_t)kt * F_DIM;
            float4 v = *(const float4*)p0;
            float4 u = *(const float4*)(p0 + 4);
            float4 cv = make_float4(tf32r(v.x), tf32r(v.y), tf32r(v.z), tf32r(v.w));
            float4 cu = make_float4(tf32r(u.x), tf32r(u.y), tf32r(u.z), tf32r(u.w));
            *(float4*)&Bs0[bkrow][bcol]     = cv;
            *(float4*)&Bs0[bkrow][bcol + 4] = cu;
            const float* p1 = b1p + (size_t)kt * F_DIM;
            v = *(const float4*)p1;
            u = *(const float4*)(p1 + 4);
            cv = make_float4(tf32r(v.x), tf32r(v.y), tf32r(v.z), tf32r(v.w));
            cu = make_float4(tf32r(u.x), tf32r(u.y), tf32r(u.z), tf32r(u.w));
            *(float4*)&Bs1[bkrow][bcol]     = cv;
            *(float4*)&Bs1[bkrow][bcol + 4] = cu;
        }
        __syncthreads();

#pragma unroll
        for (int ks = 0; ks < BK; ks += 8) {
            uint32_t a[2][4];
#pragma unroll
            for (int mt = 0; mt < 2; mt++) {
                int m0 = mbase + mt * 16 + g;
                a[mt][0] = __float_as_uint(As[ks + t4][m0]);
                a[mt][1] = __float_as_uint(As[ks + t4][m0 + 8]);
                a[mt][2] = __float_as_uint(As[ks + t4 + 4][m0]);
                a[mt][3] = __float_as_uint(As[ks + t4 + 4][m0 + 8]);
            }
#pragma unroll
            for (int nq = 0; nq < 4; nq++) {
                uint32_t b[2];
                int n0 = nbase + nq * 8 + g;
                b[0] = __float_as_uint(Bs0[ks + t4][n0]);
                b[1] = __float_as_uint(Bs0[ks + t4 + 4][n0]);
                mma8(c0[0][nq], a[0], b);
                mma8(c0[1][nq], a[1], b);
            }
#pragma unroll
            for (int nq = 0; nq < 4; nq++) {
                uint32_t b[2];
                int n0 = nbase + nq * 8 + g;
                b[0] = __float_as_uint(Bs1[ks + t4][n0]);
                b[1] = __float_as_uint(Bs1[ks + t4 + 4][n0]);
                mma8(c1[0][nq], a[0], b);
                mma8(c1[1][nq], a[1], b);
            }
        }
        __syncthreads();
    }

    // epilogue: h = silu(c0) * c1
#pragma unroll
    for (int mt = 0; mt < 2; mt++) {
        int r0 = mbase + mt * 16 + g;
#pragma unroll
        for (int nq = 0; nq < 4; nq++) {
            int col = ntile * BN + nbase + nq * 8 + t4 * 2;
            int ent = s_entry[r0];
            if (ent >= 0) {
                float a0 = c0[mt][nq][0], a1 = c0[mt][nq][1];
                float2 v;
                v.x = (a0 / (1.f + expf(-a0))) * c1[mt][nq][0];
                v.y = (a1 / (1.f + expf(-a1))) * c1[mt][nq][1];
                *(float2*)&g_h[(size_t)ent * F_DIM + col] = v;
            }
            int ent2 = s_entry[r0 + 8];
            if (ent2 >= 0) {
                float a2 = c0[mt][nq][2], a3 = c0[mt][nq][3];
                float2 v;
                v.x = (a2 / (1.f + expf(-a2))) * c1[mt][nq][2];
                v.y = (a3 / (1.f + expf(-a3))) * c1[mt][nq][3];
                *(float2*)&g_h[(size_t)ent2 * F_DIM + col] = v;
            }
        }
    }
}

// ---------------- kernel 3: grouped down-projection ----------------
// o[entry, d] = h[entry] @ wo[e]
__global__ __launch_bounds__(256) void ffn_down_kernel(const float* __restrict__ wo)
{
    int e = blockIdx.z;
    int mtile = blockIdx.y;
    int ntile = blockIdx.x;
    int nt = g_cnt[e];
    if (mtile * BM >= nt) return;

    __shared__ float As[BK][BM + APAD];
    __shared__ float Bs[BK][BN + BPAD];
    __shared__ int s_entry[BM];

    int tid = threadIdx.x;
    if (tid < BM) {
        int i = mtile * BM + tid;
        s_entry[tid] = (i < nt) ? g_entries[e * T_TOK + i] : -1;
    }
    __syncthreads();

    float c[2][4][4];
#pragma unroll
    for (int i = 0; i < 2; i++)
#pragma unroll
        for (int j = 0; j < 4; j++)
#pragma unroll
            for (int k = 0; k < 4; k++) c[i][j][k] = 0.f;

    int lrow = tid >> 1;
    int lk   = (tid & 1) * 16;
    int row_ent = (s_entry[lrow] >= 0) ? s_entry[lrow] : 0;
    const float* aptr = g_h + (size_t)row_ent * F_DIM + lk;

    int bkrow = tid >> 3;
    int bcol  = (tid & 7) * 8;
    const float* bp = wo + ((size_t)e * F_DIM + bkrow) * D_DIM + (size_t)ntile * BN + bcol;

    int lane = tid & 31, warp = tid >> 5;
    int g = lane >> 2, t4 = lane & 3;
    int wm = warp >> 1, wn = warp & 1;
    int mbase = wm * 32, nbase = wn * 32;

    for (int kt = 0; kt < F_DIM; kt += BK) {
#pragma unroll
        for (int q = 0; q < 4; q++) {
            float4 v = *(const float4*)(aptr + kt + q * 4);
            As[lk + q * 4 + 0][lrow] = tf32r(v.x);
            As[lk + q * 4 + 1][lrow] = tf32r(v.y);
            As[lk + q * 4 + 2][lrow] = tf32r(v.z);
            As[lk + q * 4 + 3][lrow] = tf32r(v.w);
        }
        {
            const float* p = bp + (size_t)kt * D_DIM;
            float4 v = *(const float4*)p;
            float4 u = *(const float4*)(p + 4);
            float4 cv = make_float4(tf32r(v.x), tf32r(v.y), tf32r(v.z), tf32r(v.w));
            float4 cu = make_float4(tf32r(u.x), tf32r(u.y), tf32r(u.z), tf32r(u.w));
            *(float4*)&Bs[bkrow][bcol]     = cv;
            *(float4*)&Bs[bkrow][bcol + 4] = cu;
        }
        __syncthreads();

#pragma unroll
        for (int ks = 0; ks < BK; ks += 8) {
            uint32_t a[2][4];
#pragma unroll
            for (int mt = 0; mt < 2; mt++) {
                int m0 = mbase + mt * 16 + g;
                a[mt][0] = __float_as_uint(As[ks + t4][m0]);
                a[mt][1] = __float_as_uint(As[ks + t4][m0 + 8]);
                a[mt][2] = __float_as_uint(As[ks + t4 + 4][m0]);
                a[mt][3] = __float_as_uint(As[ks + t4 + 4][m0 + 8]);
            }
#pragma unroll
            for (int nq = 0; nq < 4; nq++) {
                uint32_t b[2];
                int n0 = nbase + nq * 8 + g;
                b[0] = __float_as_uint(Bs[ks + t4][n0]);
                b[1] = __float_as_uint(Bs[ks + t4 + 4][n0]);
                mma8(c[0][nq], a[0], b);
                mma8(c[1][nq], a[1], b);
            }
        }
        __syncthreads();
    }

#pragma unroll
    for (int mt = 0; mt < 2; mt++) {
        int r0 = mbase + mt * 16 + g;
#pragma unroll
        for (int nq = 0; nq < 4; nq++) {
            int col = ntile * BN + nbase + nq * 8 + t4 * 2;
            int ent = s_entry[r0];
            if (ent >= 0) {
                float2 v = make_float2(c[mt][nq][0], c[mt][nq][1]);
                *(float2*)&g_o[(size_t)ent * D_DIM + col] = v;
            }
            int ent2 = s_entry[r0 + 8];
            if (ent2 >= 0) {
                float2 v = make_float2(c[mt][nq][2], c[mt][nq][3]);
                *(float2*)&g_o[(size_t)ent2 * D_DIM + col] = v;
            }
        }
    }
}

// ---------------- kernel 4: weighted combine ----------------
__global__ void combine_kernel(float* __restrict__ out) {
    int i = blockIdx.x * blockDim.x + threadIdx.x;   // over T*D/4
    int t = i >> 8;                                   // 256 float4 per token
    int c = (i & 255) * 4;
    float w0 = g_w[2 * t], w1 = g_w[2 * t + 1];
    float4 o0 = *(const float4*)&g_o[(size_t)(2 * t) * D_DIM + c];
    float4 o1 = *(const float4*)&g_o[(size_t)(2 * t + 1) * D_DIM + c];
    float4 r;
    r.x = w0 * o0.x + w1 * o1.x;
    r.y = w0 * o0.y + w1 * o1.y;
    r.z = w0 * o0.z + w1 * o1.z;
    r.w = w0 * o0.w + w1 * o1.w;
    ((float4*)out)[i] = r;
}

// ---------------- launcher ----------------
extern "C" void kernel_launch(void* const* d_in, const int* in_sizes, int n_in,
                              void* d_out, int out_size) {
    const float* x   = (const float*)d_in[0];
    const float* gw  = (const float*)d_in[1];
    const float* wi0 = (const float*)d_in[2];
    const float* wi1 = (const float*)d_in[3];
    const float* wo  = (const float*)d_in[4];
    float* out = (float*)d_out;

    zero_cnt_kernel<<<1, 32>>>();
    router_kernel<<<T_TOK / 8, 256>>>(x, gw);

    dim3 gup(F_DIM / BN, T_TOK / BM, E_NUM);   // (64, 64, 8)
    ffn_up_kernel<<<gup, 256>>>(x, wi0, wi1);

    dim3 gdn(D_DIM / BN, T_TOK / BM, E_NUM);   // (16, 64, 8)
    ffn_down_kernel<<<gdn, 256>>>(wo);

    combine_kernel<<<(T_TOK * D_DIM / 4) / 256, 256>>>(out);
}

// round 4
// speedup vs baseline: 1.0109x; 1.0109x over previous
#include <cuda_runtime.h>
#include <cstdint>
#include <math.h>

// ---------------- problem constants ----------------
#define T_TOK 8192      // B*S tokens
#define D_DIM 1024
#define F_DIM 4096
#define E_NUM 8

// ---------------- GEMM tiling ----------------
#define BM 128
#define BN 128
#define BK 32
#define AS_STRIDE 36            // BK + 4  (conflict-free A fragment reads)
#define BS_STRIDE 136           // BN + 8  (conflict-free B fragment reads)
#define A_FLOATS (BM * AS_STRIDE)       // 4608
#define B_FLOATS (BK * BS_STRIDE)       // 4352
#define UP_BUF   (A_FLOATS + 2 * B_FLOATS)   // 13312 floats
#define DN_BUF   (A_FLOATS + B_FLOATS)       // 8960 floats
#define UP_SMEM  (2 * UP_BUF * 4)            // 106496 B
#define DN_SMEM  (2 * DN_BUF * 4)            // 71680 B

// ---------------- scratch (device globals; no allocations) ----------------
__device__ float g_h[(size_t)2 * T_TOK * F_DIM];   // per-(token,slot) hidden (tf32-rounded)
__device__ int   g_entries[E_NUM * T_TOK];
__device__ int   g_cnt[E_NUM];
__device__ float g_w[2 * T_TOK];

// ---------------- helpers ----------------
__device__ __forceinline__ float tf32r(float x) {
    uint32_t u;
    asm("cvt.rna.tf32.f32 %0, %1;" : "=r"(u) : "f"(x));
    return __uint_as_float(u);
}

__device__ __forceinline__ float4 tf32r4(float4 v) {
    return make_float4(tf32r(v.x), tf32r(v.y), tf32r(v.z), tf32r(v.w));
}

__device__ __forceinline__ void mma8(float c[4], const uint32_t a[4], const uint32_t b[2]) {
    asm volatile(
        "mma.sync.aligned.m16n8k8.row.col.f32.tf32.tf32.f32 "
        "{%0,%1,%2,%3}, {%4,%5,%6,%7}, {%8,%9}, {%0,%1,%2,%3};"
        : "+f"(c[0]), "+f"(c[1]), "+f"(c[2]), "+f"(c[3])
        : "r"(a[0]), "r"(a[1]), "r"(a[2]), "r"(a[3]), "r"(b[0]), "r"(b[1]));
}

// ---------------- kernel 0: zero output + counters ----------------
__global__ void zero_init_kernel(float* __restrict__ out) {
    size_t i = (size_t)blockIdx.x * 256 + threadIdx.x;
    ((float4*)out)[i] = make_float4(0.f, 0.f, 0.f, 0.f);
    if (blockIdx.x == 0 && threadIdx.x < E_NUM) g_cnt[threadIdx.x] = 0;
}

// ---------------- kernel 1: router (warp per token) ----------------
__global__ void router_kernel(const float* __restrict__ x, const float* __restrict__ gw) {
    int warp = (blockIdx.x * blockDim.x + threadIdx.x) >> 5;
    int lane = threadIdx.x & 31;
    if (warp >= T_TOK) return;
    const float* xr = x + (size_t)warp * D_DIM;

    float acc[E_NUM];
#pragma unroll
    for (int e = 0; e < E_NUM; e++) acc[e] = 0.f;

    for (int j = lane; j < D_DIM; j += 32) {
        float xv = xr[j];
        const float4* gp = (const float4*)(gw + (size_t)j * E_NUM);
        float4 g0 = gp[0], g1 = gp[1];
        acc[0] += xv * g0.x; acc[1] += xv * g0.y; acc[2] += xv * g0.z; acc[3] += xv * g0.w;
        acc[4] += xv * g1.x; acc[5] += xv * g1.y; acc[6] += xv * g1.z; acc[7] += xv * g1.w;
    }
#pragma unroll
    for (int e = 0; e < E_NUM; e++) {
#pragma unroll
        for (int o = 16; o > 0; o >>= 1)
            acc[e] += __shfl_down_sync(0xffffffffu, acc[e], o);
    }
    if (lane == 0) {
        float v0 = -1e30f, v1 = -1e30f;
        int e0 = 0, e1 = 0;
        for (int e = 0; e < E_NUM; e++) {
            float v = acc[e];
            if (v > v0)      { v1 = v0; e1 = e0; v0 = v; e0 = e; }
            else if (v > v1) { v1 = v;  e1 = e; }
        }
        float ex = expf(v1 - v0);
        float s  = 1.f / (1.f + ex);
        g_w[warp * 2 + 0] = s;
        g_w[warp * 2 + 1] = ex * s;
        int p0 = atomicAdd(&g_cnt[e0], 1);
        g_entries[e0 * T_TOK + p0] = warp * 2 + 0;
        int p1 = atomicAdd(&g_cnt[e1], 1);
        g_entries[e1 * T_TOK + p1] = warp * 2 + 1;
    }
}

// ---------------- kernel 2: up-projection (dual-B, silu-gated) ----------------
// CTA tile M=128, N=128(per matrix). Warp tile M=64, N=32, dual accumulators.
__global__ void __launch_bounds__(256, 1) ffn_up_kernel(
    const float* __restrict__ x,
    const float* __restrict__ wi0,
    const float* __restrict__ wi1)
{
    extern __shared__ float smem[];
    int e = blockIdx.z, mtile = blockIdx.y, ntile = blockIdx.x;
    int nt = g_cnt[e];
    if (mtile * BM >= nt) return;

    __shared__ int s_ent[BM];
    int tid = threadIdx.x;
    if (tid < BM) {
        int i = mtile * BM + tid;
        s_ent[tid] = (i < nt) ? g_entries[e * T_TOK + i] : -1;
    }
    __syncthreads();

    // staging maps
    int arow = tid >> 1;
    int ahalf = (tid & 1) * 16;
    int aent = s_ent[arow];
    const float* ap = x + (size_t)((aent >= 0) ? (aent >> 1) : 0) * D_DIM + ahalf;

    int bkrow = tid >> 3;
    int bnb = (tid & 7) * 16;
    const float* b0p = wi0 + (size_t)e * D_DIM * F_DIM + (size_t)ntile * BN + bnb;
    const float* b1p = wi1 + (size_t)e * D_DIM * F_DIM + (size_t)ntile * BN + bnb;

    // fragment maps
    int lane = tid & 31, wid = tid >> 5;
    int g = lane >> 2, t4 = lane & 3;
    int mbase = (wid >> 2) * 64;
    int nbase = (wid & 3) * 32;

    float c0[4][4][4], c1[4][4][4];
#pragma unroll
    for (int a = 0; a < 4; a++)
#pragma unroll
        for (int b = 0; b < 4; b++)
#pragma unroll
            for (int k = 0; k < 4; k++) { c0[a][b][k] = 0.f; c1[a][b][k] = 0.f; }

    float4 av[4], bv0[4], bv1[4];

    auto ldg = [&](int kt) {
#pragma unroll
        for (int q = 0; q < 4; q++) av[q] = *(const float4*)(ap + kt + 4 * q);
        const float* p0 = b0p + (size_t)(kt + bkrow) * F_DIM;
        const float* p1 = b1p + (size_t)(kt + bkrow) * F_DIM;
#pragma unroll
        for (int q = 0; q < 4; q++) bv0[q] = *(const float4*)(p0 + 4 * q);
#pragma unroll
        for (int q = 0; q < 4; q++) bv1[q] = *(const float4*)(p1 + 4 * q);
    };
    auto sts = [&](float* buf) {
        float* Ad = buf + arow * AS_STRIDE + ahalf;
        float* B0d = buf + A_FLOATS + bkrow * BS_STRIDE + bnb;
        float* B1d = B0d + B_FLOATS;
#pragma unroll
        for (int q = 0; q < 4; q++) *(float4*)(Ad + 4 * q) = tf32r4(av[q]);
#pragma unroll
        for (int q = 0; q < 4; q++) *(float4*)(B0d + 4 * q) = tf32r4(bv0[q]);
#pragma unroll
        for (int q = 0; q < 4; q++) *(float4*)(B1d + 4 * q) = tf32r4(bv1[q]);
    };

    const int NIT = D_DIM / BK;  // 32
    ldg(0);
    sts(smem);
    __syncthreads();

    for (int i = 0; i < NIT; i++) {
        const float* cur = smem + (i & 1) * UP_BUF;
        if (i + 1 < NIT) ldg((i + 1) * BK);

        const float* As  = cur;
        const float* Bs0 = cur + A_FLOATS;
        const float* Bs1 = Bs0 + B_FLOATS;
#pragma unroll
        for (int ks = 0; ks < BK; ks += 8) {
            uint32_t a[4][4];
#pragma unroll
            for (int mt = 0; mt < 4; mt++) {
                const float* ar = As + (mbase + mt * 16 + g) * AS_STRIDE + ks + t4;
                a[mt][0] = __float_as_uint(ar[0]);
                a[mt][1] = __float_as_uint(ar[8 * AS_STRIDE]);
                a[mt][2] = __float_as_uint(ar[4]);
                a[mt][3] = __float_as_uint(ar[8 * AS_STRIDE + 4]);
            }
#pragma unroll
            for (int nq = 0; nq < 4; nq++) {
                int n0 = nbase + nq * 8 + g;
                uint32_t b[2];
                const float* br = Bs0 + (ks + t4) * BS_STRIDE + n0;
                b[0] = __float_as_uint(br[0]);
                b[1] = __float_as_uint(br[4 * BS_STRIDE]);
#pragma unroll
                for (int mt = 0; mt < 4; mt++) mma8(c0[mt][nq], a[mt], b);
                const float* br1 = Bs1 + (ks + t4) * BS_STRIDE + n0;
                b[0] = __float_as_uint(br1[0]);
                b[1] = __float_as_uint(br1[4 * BS_STRIDE]);
#pragma unroll
                for (int mt = 0; mt < 4; mt++) mma8(c1[mt][nq], a[mt], b);
            }
        }
        if (i + 1 < NIT) sts(smem + ((i + 1) & 1) * UP_BUF);
        __syncthreads();
    }

    // epilogue: h = silu(c0) * c1, tf32-rounded into g_h
#pragma unroll
    for (int mt = 0; mt < 4; mt++) {
        int r0 = mbase + mt * 16 + g;
#pragma unroll
        for (int nq = 0; nq < 4; nq++) {
            size_t col = (size_t)ntile * BN + nbase + nq * 8 + t4 * 2;
            int e0 = s_ent[r0];
            if (e0 >= 0) {
                float a0 = c0[mt][nq][0], a1 = c0[mt][nq][1];
                float2 v;
                v.x = tf32r((a0 / (1.f + __expf(-a0))) * c1[mt][nq][0]);
                v.y = tf32r((a1 / (1.f + __expf(-a1))) * c1[mt][nq][1]);
                *(float2*)&g_h[(size_t)e0 * F_DIM + col] = v;
            }
            int e1 = s_ent[r0 + 8];
            if (e1 >= 0) {
                float a2 = c0[mt][nq][2], a3 = c0[mt][nq][3];
                float2 v;
                v.x = tf32r((a2 / (1.f + __expf(-a2))) * c1[mt][nq][2]);
                v.y = tf32r((a3 / (1.f + __expf(-a3))) * c1[mt][nq][3]);
                *(float2*)&g_h[(size_t)e1 * F_DIM + col] = v;
            }
        }
    }
}

// ---------------- kernel 3: down-projection + fused weighted combine ----------------
__global__ void __launch_bounds__(256, 1) ffn_dn_kernel(
    const float* __restrict__ wo, float* __restrict__ out)
{
    extern __shared__ float smem[];
    int e = blockIdx.z, mtile = blockIdx.y, ntile = blockIdx.x;
    int nt = g_cnt[e];
    if (mtile * BM >= nt) return;

    __shared__ int s_ent[BM];
    __shared__ float s_w[BM];
    int tid = threadIdx.x;
    if (tid < BM) {
        int i = mtile * BM + tid;
        int ent = (i < nt) ? g_entries[e * T_TOK + i] : -1;
        s_ent[tid] = ent;
        s_w[tid] = (ent >= 0) ? g_w[ent] : 0.f;
    }
    __syncthreads();

    int arow = tid >> 1;
    int ahalf = (tid & 1) * 16;
    int aent = s_ent[arow];
    const float* ap = g_h + (size_t)((aent >= 0) ? aent : 0) * F_DIM + ahalf;

    int bkrow = tid >> 3;
    int bnb = (tid & 7) * 16;
    const float* bp = wo + (size_t)e * F_DIM * D_DIM + (size_t)ntile * BN + bnb;

    int lane = tid & 31, wid = tid >> 5;
    int g = lane >> 2, t4 = lane & 3;
    int mbase = (wid >> 2) * 64;
    int nbase = (wid & 3) * 32;

    float c[4][4][4];
#pragma unroll
    for (int a = 0; a < 4; a++)
#pragma unroll
        for (int b = 0; b < 4; b++)
#pragma unroll
            for (int k = 0; k < 4; k++) c[a][b][k] = 0.f;

    float4 av[4], bv[4];

    auto ldg = [&](int kt) {
#pragma unroll
        for (int q = 0; q < 4; q++) av[q] = *(const float4*)(ap + kt + 4 * q);
        const float* p = bp + (size_t)(kt + bkrow) * D_DIM;
#pragma unroll
        for (int q = 0; q < 4; q++) bv[q] = *(const float4*)(p + 4 * q);
    };
    auto sts = [&](float* buf) {
        float* Ad = buf + arow * AS_STRIDE + ahalf;
        float* Bd = buf + A_FLOATS + bkrow * BS_STRIDE + bnb;
#pragma unroll
        for (int q = 0; q < 4; q++) *(float4*)(Ad + 4 * q) = av[q];  // g_h already tf32
#pragma unroll
        for (int q = 0; q < 4; q++) *(float4*)(Bd + 4 * q) = tf32r4(bv[q]);
    };

    const int NIT = F_DIM / BK;  // 128
    ldg(0);
    sts(smem);
    __syncthreads();

    for (int i = 0; i < NIT; i++) {
        const float* cur = smem + (i & 1) * DN_BUF;
        if (i + 1 < NIT) ldg((i + 1) * BK);

        const float* As = cur;
        const float* Bs = cur + A_FLOATS;
#pragma unroll
        for (int ks = 0; ks < BK; ks += 8) {
            uint32_t a[4][4];
#pragma unroll
            for (int mt = 0; mt < 4; mt++) {
                const float* ar = As + (mbase + mt * 16 + g) * AS_STRIDE + ks + t4;
                a[mt][0] = __float_as_uint(ar[0]);
                a[mt][1] = __float_as_uint(ar[8 * AS_STRIDE]);
                a[mt][2] = __float_as_uint(ar[4]);
                a[mt][3] = __float_as_uint(ar[8 * AS_STRIDE + 4]);
            }
#pragma unroll
            for (int nq = 0; nq < 4; nq++) {
                int n0 = nbase + nq * 8 + g;
                uint32_t b[2];
                const float* br = Bs + (ks + t4) * BS_STRIDE + n0;
                b[0] = __float_as_uint(br[0]);
                b[1] = __float_as_uint(br[4 * BS_STRIDE]);
#pragma unroll
                for (int mt = 0; mt < 4; mt++) mma8(c[mt][nq], a[mt], b);
            }
        }
        if (i + 1 < NIT) sts(smem + ((i + 1) & 1) * DN_BUF);
        __syncthreads();
    }

    // epilogue: out[tok] += w * o  (2 commutative adds per element -> deterministic)
#pragma unroll
    for (int mt = 0; mt < 4; mt++) {
        int r0 = mbase + mt * 16 + g;
#pragma unroll
        for (int nq = 0; nq < 4; nq++) {
            size_t col = (size_t)ntile * BN + nbase + nq * 8 + t4 * 2;
            int e0 = s_ent[r0];
            if (e0 >= 0) {
                float w = s_w[r0];
                float* o = out + (size_t)(e0 >> 1) * D_DIM + col;
                atomicAdd(o,     c[mt][nq][0] * w);
                atomicAdd(o + 1, c[mt][nq][1] * w);
            }
            int e1 = s_ent[r0 + 8];
            if (e1 >= 0) {
                float w = s_w[r0 + 8];
                float* o = out + (size_t)(e1 >> 1) * D_DIM + col;
                atomicAdd(o,     c[mt][nq][2] * w);
                atomicAdd(o + 1, c[mt][nq][3] * w);
            }
        }
    }
}

// ---------------- launcher ----------------
extern "C" void kernel_launch(void* const* d_in, const int* in_sizes, int n_in,
                              void* d_out, int out_size) {
    const float* x   = (const float*)d_in[0];
    const float* gw  = (const float*)d_in[1];
    const float* wi0 = (const float*)d_in[2];
    const float* wi1 = (const float*)d_in[3];
    const float* wo  = (const float*)d_in[4];
    float* out = (float*)d_out;

    cudaFuncSetAttribute(ffn_up_kernel, cudaFuncAttributeMaxDynamicSharedMemorySize, UP_SMEM);
    cudaFuncSetAttribute(ffn_dn_kernel, cudaFuncAttributeMaxDynamicSharedMemorySize, DN_SMEM);

    zero_init_kernel<<<(T_TOK * D_DIM / 4) / 256, 256>>>(out);
    router_kernel<<<T_TOK / 8, 256>>>(x, gw);

    dim3 gup(F_DIM / BN, T_TOK / BM, E_NUM);   // (32, 64, 8)
    ffn_up_kernel<<<gup, 256, UP_SMEM>>>(x, wi0, wi1);

    dim3 gdn(D_DIM / BN, T_TOK / BM, E_NUM);   // (8, 64, 8)
    ffn_dn_kernel<<<gdn, 256, DN_SMEM>>>(wo, out);
}

// round 7
// speedup vs baseline: 1.9959x; 1.9743x over previous
#include <cuda_runtime.h>
#include <cuda_fp16.h>
#include <cstdint>
#include <math.h>

// ---------------- problem constants ----------------
#define T_TOK 8192
#define D_DIM 1024
#define F_DIM 4096
#define E_NUM 8

// ---------------- tiling ----------------
#define BM 128
#define BK 32                    // halves per k-tile (2 mma k-steps)
#define KSTR 40                  // smem row stride in halves (32 + 8 pad)
#define A_BYTES (BM * KSTR * 2)  // 10240

// up: two B tiles of 64 rows ([n][k])
#define UPB_BYTES (64 * KSTR * 2)            // 5120
#define UP_B0_OFF A_BYTES
#define UP_B1_OFF (A_BYTES + UPB_BYTES)
#define UP_STAGE  (A_BYTES + 2 * UPB_BYTES)  // 20480
#define UP_SMEM   (2 * UP_STAGE)             // 40960

// down: one B tile of 128 rows
#define DN_B_OFF A_BYTES
#define DN_STAGE (A_BYTES + BM * KSTR * 2)   // 20480
#define DN_SMEM  (2 * DN_STAGE)              // 40960

// ---------------- scratch (device globals; no allocations) ----------------
__device__ __half g_h[(size_t)2 * T_TOK * F_DIM];           // fp16 hidden
__device__ __half g_xh[(size_t)T_TOK * D_DIM];              // fp16 inputs
__device__ __half g_wi0t[(size_t)E_NUM * D_DIM * F_DIM];    // wi0^T : [e][f][d]
__device__ __half g_wi1t[(size_t)E_NUM * D_DIM * F_DIM];    // wi1^T : [e][f][d]
__device__ __half g_wot[(size_t)E_NUM * F_DIM * D_DIM];     // wo^T  : [e][d][f]
__device__ int    g_entries[E_NUM * T_TOK];
__device__ int    g_cnt[E_NUM];
__device__ float  g_w[2 * T_TOK];

// ---------------- helpers ----------------
__device__ __forceinline__ void mma16(float c[4], const uint32_t a[4], uint32_t b0, uint32_t b1) {
    asm volatile(
        "mma.sync.aligned.m16n8k16.row.col.f32.f16.f16.f32 "
        "{%0,%1,%2,%3}, {%4,%5,%6,%7}, {%8,%9}, {%0,%1,%2,%3};"
        : "+f"(c[0]), "+f"(c[1]), "+f"(c[2]), "+f"(c[3])
        : "r"(a[0]), "r"(a[1]), "r"(a[2]), "r"(a[3]), "r"(b0), "r"(b1));
}

// ---------------- kernel 0: zero output + counters ----------------
__global__ void zero_init_kernel(float* __restrict__ out) {
    size_t i = (size_t)blockIdx.x * 256 + threadIdx.x;
    ((float4*)out)[i] = make_float4(0.f, 0.f, 0.f, 0.f);
    if (blockIdx.x == 0 && threadIdx.x < E_NUM) g_cnt[threadIdx.x] = 0;
}

// ---------------- fp32 -> fp16 transpose: dst[e][c][r] = (half)src[e][r][c] ----------------
__global__ void transpose_fp16_kernel(const float* __restrict__ src, __half* __restrict__ dst,
                                      int R, int C) {
    __shared__ __half tile[32][33];
    int e = blockIdx.z;
    const float* s = src + (size_t)e * R * C;
    __half* d = dst + (size_t)e * R * C;
    int c0 = blockIdx.x * 32, r0 = blockIdx.y * 32;
    int tx = threadIdx.x, ty = threadIdx.y;
#pragma unroll
    for (int k = 0; k < 4; k++)
        tile[ty + 8 * k][tx] = __float2half_rn(s[(size_t)(r0 + ty + 8 * k) * C + c0 + tx]);
    __syncthreads();
#pragma unroll
    for (int k = 0; k < 4; k++)
        d[(size_t)(c0 + ty + 8 * k) * R + r0 + tx] = tile[tx][ty + 8 * k];
}

// ---------------- kernel 1: router (warp/token) + x fp16 conversion ----------------
__global__ void router_kernel(const float* __restrict__ x, const float* __restrict__ gw) {
    int warp = (blockIdx.x * blockDim.x + threadIdx.x) >> 5;
    int lane = threadIdx.x & 31;
    if (warp >= T_TOK) return;
    const float* xr = x + (size_t)warp * D_DIM;

    float acc[E_NUM];
#pragma unroll
    for (int e = 0; e < E_NUM; e++) acc[e] = 0.f;

    for (int j = lane; j < D_DIM; j += 32) {
        float xv = xr[j];
        g_xh[(size_t)warp * D_DIM + j] = __float2half_rn(xv);
        const float4* gp = (const float4*)(gw + (size_t)j * E_NUM);
        float4 g0 = gp[0], g1 = gp[1];
        acc[0] += xv * g0.x; acc[1] += xv * g0.y; acc[2] += xv * g0.z; acc[3] += xv * g0.w;
        acc[4] += xv * g1.x; acc[5] += xv * g1.y; acc[6] += xv * g1.z; acc[7] += xv * g1.w;
    }
#pragma unroll
    for (int e = 0; e < E_NUM; e++) {
#pragma unroll
        for (int o = 16; o > 0; o >>= 1)
            acc[e] += __shfl_down_sync(0xffffffffu, acc[e], o);
    }
    if (lane == 0) {
        float v0 = -1e30f, v1 = -1e30f;
        int e0 = 0, e1 = 0;
        for (int e = 0; e < E_NUM; e++) {
            float v = acc[e];
            if (v > v0)      { v1 = v0; e1 = e0; v0 = v; e0 = e; }
            else if (v > v1) { v1 = v;  e1 = e; }
        }
        float ex = expf(v1 - v0);
        float s  = 1.f / (1.f + ex);
        g_w[warp * 2 + 0] = s;
        g_w[warp * 2 + 1] = ex * s;
        int p0 = atomicAdd(&g_cnt[e0], 1);
        g_entries[e0 * T_TOK + p0] = warp * 2 + 0;
        int p1 = atomicAdd(&g_cnt[e1], 1);
        g_entries[e1 * T_TOK + p1] = warp * 2 + 1;
    }
}

// ---------------- kernel 2: up-projection (fp16 mma, dual-B, silu-gated) ----------------
// CTA: M=128 x 64 cols of EACH of wi0/wi1. Warp: 64x16 per matrix.
__global__ void __launch_bounds__(256, 2) ffn_up_kernel() {
    extern __shared__ char smem[];
    int e = blockIdx.z, mtile = blockIdx.y, ntile = blockIdx.x;
    int nt = g_cnt[e];
    if (mtile * BM >= nt) return;

    __shared__ int s_ent[BM];
    int tid = threadIdx.x;
    if (tid < BM) {
        int i = mtile * BM + tid;
        s_ent[tid] = (i < nt) ? g_entries[e * T_TOK + i] : -1;
    }
    __syncthreads();

    // A staging: thread -> (row, k-half): 2 uint4 (16 halves)
    int arow = tid >> 1, ah = (tid & 1) * 16;
    int ent0 = s_ent[arow];
    const __half* asrc = g_xh + (size_t)((ent0 >= 0) ? (ent0 >> 1) : 0) * D_DIM + ah;
    uint32_t adoff = (uint32_t)(arow * (KSTR * 2) + ah * 2);

    // B staging: thread -> (n-row, 8 halves): 1 uint4 per matrix. Tiles are [n][k].
    int brow = tid >> 2, bq = (tid & 3) * 8;
    const __half* b0src = g_wi0t + ((size_t)e * F_DIM + (size_t)ntile * 64 + brow) * D_DIM + bq;
    const __half* b1src = g_wi1t + ((size_t)e * F_DIM + (size_t)ntile * 64 + brow) * D_DIM + bq;
    uint32_t bdoff = (uint32_t)(brow * (KSTR * 2) + bq * 2);

    uint4 av0, av1, b0v, b1v;
    auto ldg = [&](int kt) {
        av0 = *(const uint4*)(asrc + kt);
        av1 = *(const uint4*)(asrc + kt + 8);
        b0v = *(const uint4*)(b0src + kt);
        b1v = *(const uint4*)(b1src + kt);
    };
    auto sts = [&](char* buf) {
        *(uint4*)(buf + adoff)      = av0;
        *(uint4*)(buf + adoff + 16) = av1;
        *(uint4*)(buf + UP_B0_OFF + bdoff) = b0v;
        *(uint4*)(buf + UP_B1_OFF + bdoff) = b1v;
    };

    // fragment maps (explicit mma.m16n8k16 per-lane coordinates)
    int lane = tid & 31, wid = tid >> 5;
    int g = lane >> 2, t4 = lane & 3;
    int mbase = (wid >> 2) * 64;
    int nbase = (wid & 3) * 16;

    float cA[4][2][4], cB[4][2][4];
#pragma unroll
    for (int a = 0; a < 4; a++)
#pragma unroll
        for (int b = 0; b < 2; b++)
#pragma unroll
            for (int k = 0; k < 4; k++) { cA[a][b][k] = 0.f; cB[a][b][k] = 0.f; }

    const int NIT = D_DIM / BK;  // 32
    ldg(0);
    sts(smem);
    __syncthreads();

    for (int i = 0; i < NIT; i++) {
        if (i + 1 < NIT) ldg((i + 1) * BK);

        const char* buf = smem + (i & 1) * UP_STAGE;
        const __half* As  = (const __half*)buf;
        const __half* B0s = (const __half*)(buf + UP_B0_OFF);
        const __half* B1s = (const __half*)(buf + UP_B1_OFF);
#pragma unroll
        for (int ks = 0; ks < 2; ks++) {
            int ko = ks * 16 + 2 * t4;
            uint32_t a[4][4];
#pragma unroll
            for (int mt = 0; mt < 4; mt++) {
                const __half* r0p = As + (mbase + mt * 16 + g) * KSTR + ko;
                const __half* r1p = r0p + 8 * KSTR;
                a[mt][0] = *(const uint32_t*)(r0p);
                a[mt][1] = *(const uint32_t*)(r1p);
                a[mt][2] = *(const uint32_t*)(r0p + 8);
                a[mt][3] = *(const uint32_t*)(r1p + 8);
            }
#pragma unroll
            for (int q = 0; q < 2; q++) {
                const __half* bn0 = B0s + (nbase + q * 8 + g) * KSTR + ko;
                uint32_t b00 = *(const uint32_t*)(bn0);
                uint32_t b01 = *(const uint32_t*)(bn0 + 8);
#pragma unroll
                for (int mt = 0; mt < 4; mt++) mma16(cA[mt][q], a[mt], b00, b01);
                const __half* bn1 = B1s + (nbase + q * 8 + g) * KSTR + ko;
                uint32_t b10 = *(const uint32_t*)(bn1);
                uint32_t b11 = *(const uint32_t*)(bn1 + 8);
#pragma unroll
                for (int mt = 0; mt < 4; mt++) mma16(cB[mt][q], a[mt], b10, b11);
            }
        }
        if (i + 1 < NIT) sts(smem + ((i + 1) & 1) * UP_STAGE);
        __syncthreads();
    }

    // epilogue: h = silu(cA) * cB -> g_h (fp16)
#pragma unroll
    for (int mt = 0; mt < 4; mt++) {
        int r0 = mbase + mt * 16 + g;
#pragma unroll
        for (int q = 0; q < 2; q++) {
            size_t col = (size_t)ntile * 64 + nbase + q * 8 + t4 * 2;
            int e0 = s_ent[r0];
            if (e0 >= 0) {
                float a0 = cA[mt][q][0], a1 = cA[mt][q][1];
                float h0 = (a0 / (1.f + __expf(-a0))) * cB[mt][q][0];
                float h1 = (a1 / (1.f + __expf(-a1))) * cB[mt][q][1];
                *(__half2*)&g_h[(size_t)e0 * F_DIM + col] = __floats2half2_rn(h0, h1);
            }
            int e1 = s_ent[r0 + 8];
            if (e1 >= 0) {
                float a2 = cA[mt][q][2], a3 = cA[mt][q][3];
                float h2 = (a2 / (1.f + __expf(-a2))) * cB[mt][q][2];
                float h3 = (a3 / (1.f + __expf(-a3))) * cB[mt][q][3];
                *(__half2*)&g_h[(size_t)e1 * F_DIM + col] = __floats2half2_rn(h2, h3);
            }
        }
    }
}

// ---------------- kernel 3: down-projection (fp16 mma) + fused combine ----------------
// CTA: M=128 x N=128. Warp: 64x32.
__global__ void __launch_bounds__(256, 2) ffn_dn_kernel(float* __restrict__ out) {
    extern __shared__ char smem[];
    int e = blockIdx.z, mtile = blockIdx.y, ntile = blockIdx.x;
    int nt = g_cnt[e];
    if (mtile * BM >= nt) return;

    __shared__ int s_ent[BM];
    __shared__ float s_w[BM];
    int tid = threadIdx.x;
    if (tid < BM) {
        int i = mtile * BM + tid;
        int ent = (i < nt) ? g_entries[e * T_TOK + i] : -1;
        s_ent[tid] = ent;
        s_w[tid] = (ent >= 0) ? g_w[ent] : 0.f;
    }
    __syncthreads();

    // A staging (from g_h): 2 uint4 per thread
    int arow = tid >> 1, ah = (tid & 1) * 16;
    int ent0 = s_ent[arow];
    const __half* asrc = g_h + (size_t)((ent0 >= 0) ? ent0 : 0) * F_DIM + ah;
    uint32_t adoff = (uint32_t)(arow * (KSTR * 2) + ah * 2);

    // B staging (from wo^T [d][f]): tile [n=128][k=32], 2 uint4 per thread
    int brow = tid >> 1, bqh = (tid & 1) * 16;
    const __half* bsrc = g_wot + ((size_t)e * D_DIM + (size_t)ntile * 128 + brow) * F_DIM + bqh;
    uint32_t bdoff = (uint32_t)(DN_B_OFF + brow * (KSTR * 2) + bqh * 2);

    uint4 av0, av1, bv0, bv1;
    auto ldg = [&](int kt) {
        av0 = *(const uint4*)(asrc + kt);
        av1 = *(const uint4*)(asrc + kt + 8);
        bv0 = *(const uint4*)(bsrc + kt);
        bv1 = *(const uint4*)(bsrc + kt + 8);
    };
    auto sts = [&](char* buf) {
        *(uint4*)(buf + adoff)      = av0;
        *(uint4*)(buf + adoff + 16) = av1;
        *(uint4*)(buf + bdoff)      = bv0;
        *(uint4*)(buf + bdoff + 16) = bv1;
    };

    int lane = tid & 31, wid = tid >> 5;
    int g = lane >> 2, t4 = lane & 3;
    int mbase = (wid >> 2) * 64;
    int nbase = (wid & 3) * 32;

    float c[4][4][4];
#pragma unroll
    for (int a = 0; a < 4; a++)
#pragma unroll
        for (int b = 0; b < 4; b++)
#pragma unroll
            for (int k = 0; k < 4; k++) c[a][b][k] = 0.f;

    const int NIT = F_DIM / BK;  // 128
    ldg(0);
    sts(smem);
    __syncthreads();

    for (int i = 0; i < NIT; i++) {
        if (i + 1 < NIT) ldg((i + 1) * BK);

        const char* buf = smem + (i & 1) * DN_STAGE;
        const __half* As = (const __half*)buf;
        const __half* Bs = (const __half*)(buf + DN_B_OFF);
#pragma unroll
        for (int ks = 0; ks < 2; ks++) {
            int ko = ks * 16 + 2 * t4;
            uint32_t a[4][4];
#pragma unroll
            for (int mt = 0; mt < 4; mt++) {
                const __half* r0p = As + (mbase + mt * 16 + g) * KSTR + ko;
                const __half* r1p = r0p + 8 * KSTR;
                a[mt][0] = *(const uint32_t*)(r0p);
                a[mt][1] = *(const uint32_t*)(r1p);
                a[mt][2] = *(const uint32_t*)(r0p + 8);
                a[mt][3] = *(const uint32_t*)(r1p + 8);
            }
#pragma unroll
            for (int q = 0; q < 4; q++) {
                const __half* bn = Bs + (nbase + q * 8 + g) * KSTR + ko;
                uint32_t b0 = *(const uint32_t*)(bn);
                uint32_t b1 = *(const uint32_t*)(bn + 8);
#pragma unroll
                for (int mt = 0; mt < 4; mt++) mma16(c[mt][q], a[mt], b0, b1);
            }
        }
        if (i + 1 < NIT) sts(smem + ((i + 1) & 1) * DN_STAGE);
        __syncthreads();
    }

    // epilogue: out[tok] += w * o (2 commutative adds/element -> deterministic)
#pragma unroll
    for (int mt = 0; mt < 4; mt++) {
        int r0 = mbase + mt * 16 + g;
#pragma unroll
        for (int nq = 0; nq < 4; nq++) {
            size_t col = (size_t)ntile * 128 + nbase + nq * 8 + t4 * 2;
            int e0 = s_ent[r0];
            if (e0 >= 0) {
                float w = s_w[r0];
                float* o = out + (size_t)(e0 >> 1) * D_DIM + col;
                atomicAdd(o,     c[mt][nq][0] * w);
                atomicAdd(o + 1, c[mt][nq][1] * w);
            }
            int e1 = s_ent[r0 + 8];
            if (e1 >= 0) {
                float w = s_w[r0 + 8];
                float* o = out + (size_t)(e1 >> 1) * D_DIM + col;
                atomicAdd(o,     c[mt][nq][2] * w);
                atomicAdd(o + 1, c[mt][nq][3] * w);
            }
        }
    }
}

// ---------------- launcher ----------------
extern "C" void kernel_launch(void* const* d_in, const int* in_sizes, int n_in,
                              void* d_out, int out_size) {
    const float* x   = (const float*)d_in[0];
    const float* gw  = (const float*)d_in[1];
    const float* wi0 = (const float*)d_in[2];
    const float* wi1 = (const float*)d_in[3];
    const float* wo  = (const float*)d_in[4];
    float* out = (float*)d_out;

    cudaFuncSetAttribute(ffn_up_kernel, cudaFuncAttributeMaxDynamicSharedMemorySize, UP_SMEM);
    cudaFuncSetAttribute(ffn_dn_kernel, cudaFuncAttributeMaxDynamicSharedMemorySize, DN_SMEM);

    __half* wi0t; cudaGetSymbolAddress((void**)&wi0t, g_wi0t);
    __half* wi1t; cudaGetSymbolAddress((void**)&wi1t, g_wi1t);
    __half* wot;  cudaGetSymbolAddress((void**)&wot,  g_wot);

    zero_init_kernel<<<(T_TOK * D_DIM / 4) / 256, 256>>>(out);

    dim3 tb(32, 8);
    dim3 tg_i(F_DIM / 32, D_DIM / 32, E_NUM);   // wi*: src [D][F] -> dst [F][D]
    transpose_fp16_kernel<<<tg_i, tb>>>(wi0, wi0t, D_DIM, F_DIM);
    transpose_fp16_kernel<<<tg_i, tb>>>(wi1, wi1t, D_DIM, F_DIM);
    dim3 tg_o(D_DIM / 32, F_DIM / 32, E_NUM);   // wo: src [F][D] -> dst [D][F]
    transpose_fp16_kernel<<<tg_o, tb>>>(wo, wot, F_DIM, D_DIM);

    router_kernel<<<T_TOK / 8, 256>>>(x, gw);

    dim3 gup(F_DIM / 64, T_TOK / BM, E_NUM);    // (64, 64, 8)
    ffn_up_kernel<<<gup, 256, UP_SMEM>>>();

    dim3 gdn(D_DIM / 128, T_TOK / BM, E_NUM);   // (8, 64, 8)
    ffn_dn_kernel<<<gdn, 256, DN_SMEM>>>(out);
}

// round 8
// speedup vs baseline: 2.0765x; 1.0404x over previous
#include <cuda_runtime.h>
#include <cuda_fp16.h>
#include <cstdint>
#include <math.h>

// ---------------- problem constants ----------------
#define T_TOK 8192
#define D_DIM 1024
#define F_DIM 4096
#define E_NUM 8

// ---------------- tiling ----------------
#define BM 128
#define BK 32                    // halves per k-tile (2 mma k-steps)
#define KSTR 40                  // smem row stride in halves (32 + 8 pad)
#define A_BYTES (BM * KSTR * 2)  // 10240

// up: two B tiles of 64 rows ([n][k])
#define UPB_BYTES (64 * KSTR * 2)            // 5120
#define UP_B0_OFF A_BYTES
#define UP_B1_OFF (A_BYTES + UPB_BYTES)
#define UP_STAGE  (A_BYTES + 2 * UPB_BYTES)  // 20480
#define UP_SMEM   (2 * UP_STAGE)             // 40960

// down: one B tile of 128 rows
#define DN_B_OFF A_BYTES
#define DN_STAGE (A_BYTES + BM * KSTR * 2)   // 20480
#define DN_SMEM  (2 * DN_STAGE)              // 40960

// ---------------- scratch (device globals; no allocations) ----------------
__device__ __half g_h[(size_t)2 * T_TOK * F_DIM];           // fp16 hidden
__device__ __half g_xh[(size_t)T_TOK * D_DIM];              // fp16 inputs
__device__ __half g_wi0t[(size_t)E_NUM * D_DIM * F_DIM];    // wi0^T : [e][f][d]
__device__ __half g_wi1t[(size_t)E_NUM * D_DIM * F_DIM];    // wi1^T : [e][f][d]
__device__ __half g_wot[(size_t)E_NUM * F_DIM * D_DIM];     // wo^T  : [e][d][f]
__device__ int    g_entries[E_NUM * T_TOK];
__device__ int    g_cnt[E_NUM];
__device__ float  g_w[2 * T_TOK];

// ---------------- helpers ----------------
__device__ __forceinline__ uint32_t smem_u32(const void* p) {
    uint32_t a;
    asm("{ .reg .u64 t; cvta.to.shared.u64 t, %1; cvt.u32.u64 %0, t; }" : "=r"(a) : "l"(p));
    return a;
}

#define CPA16(dst, src) \
    asm volatile("cp.async.cg.shared.global [%0], [%1], 16;" :: "r"(dst), "l"(src) : "memory")
#define CP_COMMIT() asm volatile("cp.async.commit_group;" ::: "memory")
#define CP_WAIT0()  asm volatile("cp.async.wait_group 0;" ::: "memory")

__device__ __forceinline__ void mma16(float c[4], const uint32_t a[4], uint32_t b0, uint32_t b1) {
    asm volatile(
        "mma.sync.aligned.m16n8k16.row.col.f32.f16.f16.f32 "
        "{%0,%1,%2,%3}, {%4,%5,%6,%7}, {%8,%9}, {%0,%1,%2,%3};"
        : "+f"(c[0]), "+f"(c[1]), "+f"(c[2]), "+f"(c[3])
        : "r"(a[0]), "r"(a[1]), "r"(a[2]), "r"(a[3]), "r"(b0), "r"(b1));
}

// ---------------- kernel 0: zero output + counters ----------------
__global__ void zero_init_kernel(float* __restrict__ out) {
    size_t i = (size_t)blockIdx.x * 256 + threadIdx.x;
    ((float4*)out)[i] = make_float4(0.f, 0.f, 0.f, 0.f);
    if (blockIdx.x == 0 && threadIdx.x < E_NUM) g_cnt[threadIdx.x] = 0;
}

// ---------------- fp32 -> fp16 transpose: dst[e][c][r] = (half)src[e][r][c] ----------------
__global__ void transpose_fp16_kernel(const float* __restrict__ src, __half* __restrict__ dst,
                                      int R, int C) {
    __shared__ __half tile[32][33];
    int e = blockIdx.z;
    const float* s = src + (size_t)e * R * C;
    __half* d = dst + (size_t)e * R * C;
    int c0 = blockIdx.x * 32, r0 = blockIdx.y * 32;
    int tx = threadIdx.x, ty = threadIdx.y;
#pragma unroll
    for (int k = 0; k < 4; k++)
        tile[ty + 8 * k][tx] = __float2half_rn(s[(size_t)(r0 + ty + 8 * k) * C + c0 + tx]);
    __syncthreads();
#pragma unroll
    for (int k = 0; k < 4; k++)
        d[(size_t)(c0 + ty + 8 * k) * R + r0 + tx] = tile[tx][ty + 8 * k];
}

// ---------------- kernel 1: router (warp/token) + x fp16 conversion ----------------
__global__ void router_kernel(const float* __restrict__ x, const float* __restrict__ gw) {
    int warp = (blockIdx.x * blockDim.x + threadIdx.x) >> 5;
    int lane = threadIdx.x & 31;
    if (warp >= T_TOK) return;
    const float* xr = x + (size_t)warp * D_DIM;

    float acc[E_NUM];
#pragma unroll
    for (int e = 0; e < E_NUM; e++) acc[e] = 0.f;

    for (int j = lane; j < D_DIM; j += 32) {
        float xv = xr[j];
        g_xh[(size_t)warp * D_DIM + j] = __float2half_rn(xv);
        const float4* gp = (const float4*)(gw + (size_t)j * E_NUM);
        float4 g0 = gp[0], g1 = gp[1];
        acc[0] += xv * g0.x; acc[1] += xv * g0.y; acc[2] += xv * g0.z; acc[3] += xv * g0.w;
        acc[4] += xv * g1.x; acc[5] += xv * g1.y; acc[6] += xv * g1.z; acc[7] += xv * g1.w;
    }
#pragma unroll
    for (int e = 0; e < E_NUM; e++) {
#pragma unroll
        for (int o = 16; o > 0; o >>= 1)
            acc[e] += __shfl_down_sync(0xffffffffu, acc[e], o);
    }
    if (lane == 0) {
        float v0 = -1e30f, v1 = -1e30f;
        int e0 = 0, e1 = 0;
        for (int e = 0; e < E_NUM; e++) {
            float v = acc[e];
            if (v > v0)      { v1 = v0; e1 = e0; v0 = v; e0 = e; }
            else if (v > v1) { v1 = v;  e1 = e; }
        }
        float ex = expf(v1 - v0);
        float s  = 1.f / (1.f + ex);
        g_w[warp * 2 + 0] = s;
        g_w[warp * 2 + 1] = ex * s;
        int p0 = atomicAdd(&g_cnt[e0], 1);
        g_entries[e0 * T_TOK + p0] = warp * 2 + 0;
        int p1 = atomicAdd(&g_cnt[e1], 1);
        g_entries[e1 * T_TOK + p1] = warp * 2 + 1;
    }
}

// ---------------- kernel 2: up-projection (fp16 mma, dual-B, silu-gated) ----------------
// CTA: M=128 x 64 cols of EACH of wi0/wi1. Warp: 64x16 per matrix.
__global__ void __launch_bounds__(256, 2) ffn_up_kernel() {
    extern __shared__ char smem[];
    int e = blockIdx.z, mtile = blockIdx.y, ntile = blockIdx.x;
    int nt = g_cnt[e];
    if (mtile * BM >= nt) return;

    __shared__ int s_ent[BM];
    int tid = threadIdx.x;
    if (tid < BM) {
        int i = mtile * BM + tid;
        s_ent[tid] = (i < nt) ? g_entries[e * T_TOK + i] : -1;
    }
    __syncthreads();

    uint32_t dyn = smem_u32(smem);

    // A staging: thread -> (row, k-half): 2x16B
    int arow = tid >> 1, ah = (tid & 1) * 16;
    int ent0 = s_ent[arow];
    const __half* asrc = g_xh + (size_t)((ent0 >= 0) ? (ent0 >> 1) : 0) * D_DIM + ah;
    uint32_t adoff = (uint32_t)(arow * (KSTR * 2) + ah * 2);

    // B staging: thread -> (n-row, 8 halves): 1x16B per matrix. Tiles are [n][k].
    int brow = tid >> 2, bq = (tid & 3) * 8;
    const __half* b0src = g_wi0t + ((size_t)e * F_DIM + (size_t)ntile * 64 + brow) * D_DIM + bq;
    const __half* b1src = g_wi1t + ((size_t)e * F_DIM + (size_t)ntile * 64 + brow) * D_DIM + bq;
    uint32_t bdoff = (uint32_t)(brow * (KSTR * 2) + bq * 2);

    auto issue = [&](int i) {
        uint32_t sb = dyn + (i & 1) * UP_STAGE;
        int kt = i * BK;
        CPA16(sb + adoff, asrc + kt);
        CPA16(sb + adoff + 16, asrc + kt + 8);
        CPA16(sb + UP_B0_OFF + bdoff, b0src + kt);
        CPA16(sb + UP_B1_OFF + bdoff, b1src + kt);
        CP_COMMIT();
    };

    // fragment maps (explicit mma.m16n8k16 per-lane coordinates)
    int lane = tid & 31, wid = tid >> 5;
    int g = lane >> 2, t4 = lane & 3;
    int mbase = (wid >> 2) * 64;
    int nbase = (wid & 3) * 16;

    float cA[4][2][4], cB[4][2][4];
#pragma unroll
    for (int a = 0; a < 4; a++)
#pragma unroll
        for (int b = 0; b < 2; b++)
#pragma unroll
            for (int k = 0; k < 4; k++) { cA[a][b][k] = 0.f; cB[a][b][k] = 0.f; }

    const int NIT = D_DIM / BK;  // 32
    issue(0);
    CP_WAIT0();
    __syncthreads();

    for (int i = 0; i < NIT; i++) {
        if (i + 1 < NIT) issue(i + 1);

        const char* buf = smem + (i & 1) * UP_STAGE;
        const __half* As  = (const __half*)buf;
        const __half* B0s = (const __half*)(buf + UP_B0_OFF);
        const __half* B1s = (const __half*)(buf + UP_B1_OFF);
#pragma unroll
        for (int ks = 0; ks < 2; ks++) {
            int ko = ks * 16 + 2 * t4;
            uint32_t a[4][4];
#pragma unroll
            for (int mt = 0; mt < 4; mt++) {
                const __half* r0p = As + (mbase + mt * 16 + g) * KSTR + ko;
                const __half* r1p = r0p + 8 * KSTR;
                a[mt][0] = *(const uint32_t*)(r0p);
                a[mt][1] = *(const uint32_t*)(r1p);
                a[mt][2] = *(const uint32_t*)(r0p + 8);
                a[mt][3] = *(const uint32_t*)(r1p + 8);
            }
#pragma unroll
            for (int q = 0; q < 2; q++) {
                const __half* bn0 = B0s + (nbase + q * 8 + g) * KSTR + ko;
                uint32_t b00 = *(const uint32_t*)(bn0);
                uint32_t b01 = *(const uint32_t*)(bn0 + 8);
#pragma unroll
                for (int mt = 0; mt < 4; mt++) mma16(cA[mt][q], a[mt], b00, b01);
                const __half* bn1 = B1s + (nbase + q * 8 + g) * KSTR + ko;
                uint32_t b10 = *(const uint32_t*)(bn1);
                uint32_t b11 = *(const uint32_t*)(bn1 + 8);
#pragma unroll
                for (int mt = 0; mt < 4; mt++) mma16(cB[mt][q], a[mt], b10, b11);
            }
        }
        if (i + 1 < NIT) CP_WAIT0();
        __syncthreads();
    }

    // epilogue: h = silu(cA) * cB -> g_h (fp16)
#pragma unroll
    for (int mt = 0; mt < 4; mt++) {
        int r0 = mbase + mt * 16 + g;
#pragma unroll
        for (int q = 0; q < 2; q++) {
            size_t col = (size_t)ntile * 64 + nbase + q * 8 + t4 * 2;
            int e0 = s_ent[r0];
            if (e0 >= 0) {
                float a0 = cA[mt][q][0], a1 = cA[mt][q][1];
                float h0 = (a0 / (1.f + __expf(-a0))) * cB[mt][q][0];
                float h1 = (a1 / (1.f + __expf(-a1))) * cB[mt][q][1];
                *(__half2*)&g_h[(size_t)e0 * F_DIM + col] = __floats2half2_rn(h0, h1);
            }
            int e1 = s_ent[r0 + 8];
            if (e1 >= 0) {
                float a2 = cA[mt][q][2], a3 = cA[mt][q][3];
                float h2 = (a2 / (1.f + __expf(-a2))) * cB[mt][q][2];
                float h3 = (a3 / (1.f + __expf(-a3))) * cB[mt][q][3];
                *(__half2*)&g_h[(size_t)e1 * F_DIM + col] = __floats2half2_rn(h2, h3);
            }
        }
    }
}

// ---------------- kernel 3: down-projection (fp16 mma) + fused combine ----------------
// CTA: M=128 x N=128. Warp: 64x32.
__global__ void __launch_bounds__(256, 2) ffn_dn_kernel(float* __restrict__ out) {
    extern __shared__ char smem[];
    int e = blockIdx.z, mtile = blockIdx.y, ntile = blockIdx.x;
    int nt = g_cnt[e];
    if (mtile * BM >= nt) return;

    __shared__ int s_ent[BM];
    __shared__ float s_w[BM];
    int tid = threadIdx.x;
    if (tid < BM) {
        int i = mtile * BM + tid;
        int ent = (i < nt) ? g_entries[e * T_TOK + i] : -1;
        s_ent[tid] = ent;
        s_w[tid] = (ent >= 0) ? g_w[ent] : 0.f;
    }
    __syncthreads();

    uint32_t dyn = smem_u32(smem);

    // A staging (from g_h): 2x16B per thread
    int arow = tid >> 1, ah = (tid & 1) * 16;
    int ent0 = s_ent[arow];
    const __half* asrc = g_h + (size_t)((ent0 >= 0) ? ent0 : 0) * F_DIM + ah;
    uint32_t adoff = (uint32_t)(arow * (KSTR * 2) + ah * 2);

    // B staging (from wo^T [d][f]): tile [n=128][k=32], 2x16B per thread
    int brow = tid >> 1, bqh = (tid & 1) * 16;
    const __half* bsrc = g_wot + ((size_t)e * D_DIM + (size_t)ntile * 128 + brow) * F_DIM + bqh;
    uint32_t bdoff = (uint32_t)(DN_B_OFF + brow * (KSTR * 2) + bqh * 2);

    auto issue = [&](int i) {
        uint32_t sb = dyn + (i & 1) * DN_STAGE;
        int kt = i * BK;
        CPA16(sb + adoff, asrc + kt);
        CPA16(sb + adoff + 16, asrc + kt + 8);
        CPA16(sb + bdoff, bsrc + kt);
        CPA16(sb + bdoff + 16, bsrc + kt + 8);
        CP_COMMIT();
    };

    int lane = tid & 31, wid = tid >> 5;
    int g = lane >> 2, t4 = lane & 3;
    int mbase = (wid >> 2) * 64;
    int nbase = (wid & 3) * 32;

    float c[4][4][4];
#pragma unroll
    for (int a = 0; a < 4; a++)
#pragma unroll
        for (int b = 0; b < 4; b++)
#pragma unroll
            for (int k = 0; k < 4; k++) c[a][b][k] = 0.f;

    const int NIT = F_DIM / BK;  // 128
    issue(0);
    CP_WAIT0();
    __syncthreads();

    for (int i = 0; i < NIT; i++) {
        if (i + 1 < NIT) issue(i + 1);

        const char* buf = smem + (i & 1) * DN_STAGE;
        const __half* As = (const __half*)buf;
        const __half* Bs = (const __half*)(buf + DN_B_OFF);
#pragma unroll
        for (int ks = 0; ks < 2; ks++) {
            int ko = ks * 16 + 2 * t4;
            uint32_t a[4][4];
#pragma unroll
            for (int mt = 0; mt < 4; mt++) {
                const __half* r0p = As + (mbase + mt * 16 + g) * KSTR + ko;
                const __half* r1p = r0p + 8 * KSTR;
                a[mt][0] = *(const uint32_t*)(r0p);
                a[mt][1] = *(const uint32_t*)(r1p);
                a[mt][2] = *(const uint32_t*)(r0p + 8);
                a[mt][3] = *(const uint32_t*)(r1p + 8);
            }
#pragma unroll
            for (int q = 0; q < 4; q++) {
                const __half* bn = Bs + (nbase + q * 8 + g) * KSTR + ko;
                uint32_t b0 = *(const uint32_t*)(bn);
                uint32_t b1 = *(const uint32_t*)(bn + 8);
#pragma unroll
                for (int mt = 0; mt < 4; mt++) mma16(c[mt][q], a[mt], b0, b1);
            }
        }
        if (i + 1 < NIT) CP_WAIT0();
        __syncthreads();
    }

    // epilogue: out[tok] += w * o (2 commutative adds/element -> deterministic)
#pragma unroll
    for (int mt = 0; mt < 4; mt++) {
        int r0 = mbase + mt * 16 + g;
#pragma unroll
        for (int nq = 0; nq < 4; nq++) {
            size_t col = (size_t)ntile * 128 + nbase + nq * 8 + t4 * 2;
            int e0 = s_ent[r0];
            if (e0 >= 0) {
                float w = s_w[r0];
                float* o = out + (size_t)(e0 >> 1) * D_DIM + col;
                atomicAdd(o,     c[mt][nq][0] * w);
                atomicAdd(o + 1, c[mt][nq][1] * w);
            }
            int e1 = s_ent[r0 + 8];
            if (e1 >= 0) {
                float w = s_w[r0 + 8];
                float* o = out + (size_t)(e1 >> 1) * D_DIM + col;
                atomicAdd(o,     c[mt][nq][2] * w);
                atomicAdd(o + 1, c[mt][nq][3] * w);
            }
        }
    }
}

// ---------------- launcher ----------------
extern "C" void kernel_launch(void* const* d_in, const int* in_sizes, int n_in,
                              void* d_out, int out_size) {
    const float* x   = (const float*)d_in[0];
    const float* gw  = (const float*)d_in[1];
    const float* wi0 = (const float*)d_in[2];
    const float* wi1 = (const float*)d_in[3];
    const float* wo  = (const float*)d_in[4];
    float* out = (float*)d_out;

    cudaFuncSetAttribute(ffn_up_kernel, cudaFuncAttributeMaxDynamicSharedMemorySize, UP_SMEM);
    cudaFuncSetAttribute(ffn_dn_kernel, cudaFuncAttributeMaxDynamicSharedMemorySize, DN_SMEM);

    __half* wi0t; cudaGetSymbolAddress((void**)&wi0t, g_wi0t);
    __half* wi1t; cudaGetSymbolAddress((void**)&wi1t, g_wi1t);
    __half* wot;  cudaGetSymbolAddress((void**)&wot,  g_wot);

    zero_init_kernel<<<(T_TOK * D_DIM / 4) / 256, 256>>>(out);

    dim3 tb(32, 8);
    dim3 tg_i(F_DIM / 32, D_DIM / 32, E_NUM);   // wi*: src [D][F] -> dst [F][D]
    transpose_fp16_kernel<<<tg_i, tb>>>(wi0, wi0t, D_DIM, F_DIM);
    transpose_fp16_kernel<<<tg_i, tb>>>(wi1, wi1t, D_DIM, F_DIM);
    dim3 tg_o(D_DIM / 32, F_DIM / 32, E_NUM);   // wo: src [F][D] -> dst [D][F]
    transpose_fp16_kernel<<<tg_o, tb>>>(wo, wot, F_DIM, D_DIM);

    router_kernel<<<T_TOK / 8, 256>>>(x, gw);

    dim3 gup(F_DIM / 64, T_TOK / BM, E_NUM);    // (64, 64, 8)
    ffn_up_kernel<<<gup, 256, UP_SMEM>>>();

    dim3 gdn(D_DIM / 128, T_TOK / BM, E_NUM);   // (8, 64, 8)
    ffn_dn_kernel<<<gdn, 256, DN_SMEM>>>(out);
}

// round 9
// speedup vs baseline: 2.1596x; 1.0400x over previous
#include <cuda_runtime.h>
#include <cuda_fp16.h>
#include <cstdint>
#include <math.h>

// ---------------- problem constants ----------------
#define T_TOK 8192
#define D_DIM 1024
#define F_DIM 4096
#define E_NUM 8

// ---------------- tiling ----------------
#define BM 128
#define BK 32                    // halves per k-tile (2 mma k-steps)
#define KSTR 40                  // smem row stride in halves (32 + 8 pad)
#define A_BYTES (BM * KSTR * 2)  // 10240

// up: two B tiles of 64 rows ([n][k])
#define UPB_BYTES (64 * KSTR * 2)            // 5120
#define UP_B0_OFF A_BYTES
#define UP_B1_OFF (A_BYTES + UPB_BYTES)
#define UP_STAGE  (A_BYTES + 2 * UPB_BYTES)  // 20480
#define UP_SMEM   (3 * UP_STAGE)             // 61440 (3-stage pipeline)

// down: one B tile of 128 rows
#define DN_B_OFF A_BYTES
#define DN_STAGE (A_BYTES + BM * KSTR * 2)   // 20480
#define DN_SMEM  (3 * DN_STAGE)              // 61440

// ---------------- scratch (device globals; no allocations) ----------------
__device__ __half g_h[(size_t)2 * T_TOK * F_DIM];           // fp16 hidden
__device__ __half g_xh[(size_t)T_TOK * D_DIM];              // fp16 inputs
__device__ __half g_wi0t[(size_t)E_NUM * D_DIM * F_DIM];    // wi0^T : [e][f][d]
__device__ __half g_wi1t[(size_t)E_NUM * D_DIM * F_DIM];    // wi1^T : [e][f][d]
__device__ __half g_wot[(size_t)E_NUM * F_DIM * D_DIM];     // wo^T  : [e][d][f]
__device__ int    g_entries[E_NUM * T_TOK];
__device__ int    g_cnt[E_NUM];
__device__ float  g_w[2 * T_TOK];

// ---------------- helpers ----------------
__device__ __forceinline__ uint32_t smem_u32(const void* p) {
    uint32_t a;
    asm("{ .reg .u64 t; cvta.to.shared.u64 t, %1; cvt.u32.u64 %0, t; }" : "=r"(a) : "l"(p));
    return a;
}

#define CPA16(dst, src) \
    asm volatile("cp.async.cg.shared.global [%0], [%1], 16;" :: "r"(dst), "l"(src) : "memory")
#define CP_COMMIT() asm volatile("cp.async.commit_group;" ::: "memory")
#define CP_WAIT1()  asm volatile("cp.async.wait_group 1;" ::: "memory")

__device__ __forceinline__ void mma16(float c[4], const uint32_t a[4], uint32_t b0, uint32_t b1) {
    asm volatile(
        "mma.sync.aligned.m16n8k16.row.col.f32.f16.f16.f32 "
        "{%0,%1,%2,%3}, {%4,%5,%6,%7}, {%8,%9}, {%0,%1,%2,%3};"
        : "+f"(c[0]), "+f"(c[1]), "+f"(c[2]), "+f"(c[3])
        : "r"(a[0]), "r"(a[1]), "r"(a[2]), "r"(a[3]), "r"(b0), "r"(b1));
}

// ---------------- kernel 0: zero output + counters ----------------
__global__ void zero_init_kernel(float* __restrict__ out) {
    size_t i = (size_t)blockIdx.x * 256 + threadIdx.x;
    ((float4*)out)[i] = make_float4(0.f, 0.f, 0.f, 0.f);
    if (blockIdx.x == 0 && threadIdx.x < E_NUM) g_cnt[threadIdx.x] = 0;
}

// ---------------- fp32 -> fp16 transpose: dst[e][c][r] = (half)src[e][r][c] ----------------
__global__ void transpose_fp16_kernel(const float* __restrict__ src, __half* __restrict__ dst,
                                      int R, int C) {
    __shared__ __half tile[32][33];
    int e = blockIdx.z;
    const float* s = src + (size_t)e * R * C;
    __half* d = dst + (size_t)e * R * C;
    int c0 = blockIdx.x * 32, r0 = blockIdx.y * 32;
    int tx = threadIdx.x, ty = threadIdx.y;
#pragma unroll
    for (int k = 0; k < 4; k++)
        tile[ty + 8 * k][tx] = __float2half_rn(s[(size_t)(r0 + ty + 8 * k) * C + c0 + tx]);
    __syncthreads();
#pragma unroll
    for (int k = 0; k < 4; k++)
        d[(size_t)(c0 + ty + 8 * k) * R + r0 + tx] = tile[tx][ty + 8 * k];
}

// ---------------- kernel 1: router (warp/token) + x fp16 conversion ----------------
__global__ void router_kernel(const float* __restrict__ x, const float* __restrict__ gw) {
    int warp = (blockIdx.x * blockDim.x + threadIdx.x) >> 5;
    int lane = threadIdx.x & 31;
    if (warp >= T_TOK) return;
    const float* xr = x + (size_t)warp * D_DIM;

    float acc[E_NUM];
#pragma unroll
    for (int e = 0; e < E_NUM; e++) acc[e] = 0.f;

    for (int j = lane; j < D_DIM; j += 32) {
        float xv = xr[j];
        g_xh[(size_t)warp * D_DIM + j] = __float2half_rn(xv);
        const float4* gp = (const float4*)(gw + (size_t)j * E_NUM);
        float4 g0 = gp[0], g1 = gp[1];
        acc[0] += xv * g0.x; acc[1] += xv * g0.y; acc[2] += xv * g0.z; acc[3] += xv * g0.w;
        acc[4] += xv * g1.x; acc[5] += xv * g1.y; acc[6] += xv * g1.z; acc[7] += xv * g1.w;
    }
#pragma unroll
    for (int e = 0; e < E_NUM; e++) {
#pragma unroll
        for (int o = 16; o > 0; o >>= 1)
            acc[e] += __shfl_down_sync(0xffffffffu, acc[e], o);
    }
    if (lane == 0) {
        float v0 = -1e30f, v1 = -1e30f;
        int e0 = 0, e1 = 0;
        for (int e = 0; e < E_NUM; e++) {
            float v = acc[e];
            if (v > v0)      { v1 = v0; e1 = e0; v0 = v; e0 = e; }
            else if (v > v1) { v1 = v;  e1 = e; }
        }
        float ex = expf(v1 - v0);
        float s  = 1.f / (1.f + ex);
        g_w[warp * 2 + 0] = s;
        g_w[warp * 2 + 1] = ex * s;
        int p0 = atomicAdd(&g_cnt[e0], 1);
        g_entries[e0 * T_TOK + p0] = warp * 2 + 0;
        int p1 = atomicAdd(&g_cnt[e1], 1);
        g_entries[e1 * T_TOK + p1] = warp * 2 + 1;
    }
}

// ---------------- kernel 2: up-projection (fp16 mma, dual-B, silu-gated) ----------------
// CTA: M=128 x 64 cols of EACH of wi0/wi1. Warp: 64x16 per matrix.
__global__ void __launch_bounds__(256, 2) ffn_up_kernel() {
    extern __shared__ char smem[];
    int e = blockIdx.z, mtile = blockIdx.y, ntile = blockIdx.x;
    int nt = g_cnt[e];
    if (mtile * BM >= nt) return;

    __shared__ int s_ent[BM];
    int tid = threadIdx.x;
    if (tid < BM) {
        int i = mtile * BM + tid;
        s_ent[tid] = (i < nt) ? g_entries[e * T_TOK + i] : -1;
    }
    __syncthreads();

    uint32_t dyn = smem_u32(smem);

    // A staging: thread -> (row, k-half): 2x16B
    int arow = tid >> 1, ah = (tid & 1) * 16;
    int ent0 = s_ent[arow];
    const __half* asrc = g_xh + (size_t)((ent0 >= 0) ? (ent0 >> 1) : 0) * D_DIM + ah;
    uint32_t adoff = (uint32_t)(arow * (KSTR * 2) + ah * 2);

    // B staging: thread -> (n-row, 8 halves): 1x16B per matrix. Tiles are [n][k].
    int brow = tid >> 2, bq = (tid & 3) * 8;
    const __half* b0src = g_wi0t + ((size_t)e * F_DIM + (size_t)ntile * 64 + brow) * D_DIM + bq;
    const __half* b1src = g_wi1t + ((size_t)e * F_DIM + (size_t)ntile * 64 + brow) * D_DIM + bq;
    uint32_t bdoff = (uint32_t)(brow * (KSTR * 2) + bq * 2);

    auto issue = [&](int i) {
        uint32_t sb = dyn + (i % 3) * UP_STAGE;
        int kt = i * BK;
        CPA16(sb + adoff, asrc + kt);
        CPA16(sb + adoff + 16, asrc + kt + 8);
        CPA16(sb + UP_B0_OFF + bdoff, b0src + kt);
        CPA16(sb + UP_B1_OFF + bdoff, b1src + kt);
        CP_COMMIT();
    };

    // fragment maps (explicit mma.m16n8k16 per-lane coordinates)
    int lane = tid & 31, wid = tid >> 5;
    int g = lane >> 2, t4 = lane & 3;
    int mbase = (wid >> 2) * 64;
    int nbase = (wid & 3) * 16;

    float cA[4][2][4], cB[4][2][4];
#pragma unroll
    for (int a = 0; a < 4; a++)
#pragma unroll
        for (int b = 0; b < 2; b++)
#pragma unroll
            for (int k = 0; k < 4; k++) { cA[a][b][k] = 0.f; cB[a][b][k] = 0.f; }

    const int NIT = D_DIM / BK;  // 32
    issue(0);
    issue(1);
    CP_WAIT1();          // group 0 complete
    __syncthreads();

    for (int i = 0; i < NIT; i++) {
        if (i + 2 < NIT) issue(i + 2); else CP_COMMIT();  // keep group count aligned

        const char* buf = smem + (i % 3) * UP_STAGE;
        const __half* As  = (const __half*)buf;
        const __half* B0s = (const __half*)(buf + UP_B0_OFF);
        const __half* B1s = (const __half*)(buf + UP_B1_OFF);
#pragma unroll
        for (int ks = 0; ks < 2; ks++) {
            int ko = ks * 16 + 2 * t4;
            uint32_t a[4][4];
#pragma unroll
            for (int mt = 0; mt < 4; mt++) {
                const __half* r0p = As + (mbase + mt * 16 + g) * KSTR + ko;
                const __half* r1p = r0p + 8 * KSTR;
                a[mt][0] = *(const uint32_t*)(r0p);
                a[mt][1] = *(const uint32_t*)(r1p);
                a[mt][2] = *(const uint32_t*)(r0p + 8);
                a[mt][3] = *(const uint32_t*)(r1p + 8);
            }
#pragma unroll
            for (int q = 0; q < 2; q++) {
                const __half* bn0 = B0s + (nbase + q * 8 + g) * KSTR + ko;
                uint32_t b00 = *(const uint32_t*)(bn0);
                uint32_t b01 = *(const uint32_t*)(bn0 + 8);
#pragma unroll
                for (int mt = 0; mt < 4; mt++) mma16(cA[mt][q], a[mt], b00, b01);
                const __half* bn1 = B1s + (nbase + q * 8 + g) * KSTR + ko;
                uint32_t b10 = *(const uint32_t*)(bn1);
                uint32_t b11 = *(const uint32_t*)(bn1 + 8);
#pragma unroll
                for (int mt = 0; mt < 4; mt++) mma16(cB[mt][q], a[mt], b10, b11);
            }
        }
        CP_WAIT1();      // group i+1 complete; i+2 may still fly
        __syncthreads();
    }

    // epilogue: h = silu(cA) * cB -> g_h (fp16)
#pragma unroll
    for (int mt = 0; mt < 4; mt++) {
        int r0 = mbase + mt * 16 + g;
#pragma unroll
        for (int q = 0; q < 2; q++) {
            size_t col = (size_t)ntile * 64 + nbase + q * 8 + t4 * 2;
            int e0 = s_ent[r0];
            if (e0 >= 0) {
                float a0 = cA[mt][q][0], a1 = cA[mt][q][1];
                float h0 = (a0 / (1.f + __expf(-a0))) * cB[mt][q][0];
                float h1 = (a1 / (1.f + __expf(-a1))) * cB[mt][q][1];
                *(__half2*)&g_h[(size_t)e0 * F_DIM + col] = __floats2half2_rn(h0, h1);
            }
            int e1 = s_ent[r0 + 8];
            if (e1 >= 0) {
                float a2 = cA[mt][q][2], a3 = cA[mt][q][3];
                float h2 = (a2 / (1.f + __expf(-a2))) * cB[mt][q][2];
                float h3 = (a3 / (1.f + __expf(-a3))) * cB[mt][q][3];
                *(__half2*)&g_h[(size_t)e1 * F_DIM + col] = __floats2half2_rn(h2, h3);
            }
        }
    }
}

// ---------------- kernel 3: down-projection (fp16 mma) + fused combine ----------------
// CTA: M=128 x N=128. Warp: 64x32.
__global__ void __launch_bounds__(256, 2) ffn_dn_kernel(float* __restrict__ out) {
    extern __shared__ char smem[];
    int e = blockIdx.z, mtile = blockIdx.y, ntile = blockIdx.x;
    int nt = g_cnt[e];
    if (mtile * BM >= nt) return;

    __shared__ int s_ent[BM];
    __shared__ float s_w[BM];
    int tid = threadIdx.x;
    if (tid < BM) {
        int i = mtile * BM + tid;
        int ent = (i < nt) ? g_entries[e * T_TOK + i] : -1;
        s_ent[tid] = ent;
        s_w[tid] = (ent >= 0) ? g_w[ent] : 0.f;
    }
    __syncthreads();

    uint32_t dyn = smem_u32(smem);

    // A staging (from g_h): 2x16B per thread
    int arow = tid >> 1, ah = (tid & 1) * 16;
    int ent0 = s_ent[arow];
    const __half* asrc = g_h + (size_t)((ent0 >= 0) ? ent0 : 0) * F_DIM + ah;
    uint32_t adoff = (uint32_t)(arow * (KSTR * 2) + ah * 2);

    // B staging (from wo^T [d][f]): tile [n=128][k=32], 2x16B per thread
    int brow = tid >> 1, bqh = (tid & 1) * 16;
    const __half* bsrc = g_wot + ((size_t)e * D_DIM + (size_t)ntile * 128 + brow) * F_DIM + bqh;
    uint32_t bdoff = (uint32_t)(DN_B_OFF + brow * (KSTR * 2) + bqh * 2);

    auto issue = [&](int i) {
        uint32_t sb = dyn + (i % 3) * DN_STAGE;
        int kt = i * BK;
        CPA16(sb + adoff, asrc + kt);
        CPA16(sb + adoff + 16, asrc + kt + 8);
        CPA16(sb + bdoff, bsrc + kt);
        CPA16(sb + bdoff + 16, bsrc + kt + 8);
        CP_COMMIT();
    };

    int lane = tid & 31, wid = tid >> 5;
    int g = lane >> 2, t4 = lane & 3;
    int mbase = (wid >> 2) * 64;
    int nbase = (wid & 3) * 32;

    float c[4][4][4];
#pragma unroll
    for (int a = 0; a < 4; a++)
#pragma unroll
        for (int b = 0; b < 4; b++)
#pragma unroll
            for (int k = 0; k < 4; k++) c[a][b][k] = 0.f;

    const int NIT = F_DIM / BK;  // 128
    issue(0);
    issue(1);
    CP_WAIT1();
    __syncthreads();

    for (int i = 0; i < NIT; i++) {
        if (i + 2 < NIT) issue(i + 2); else CP_COMMIT();

        const char* buf = smem + (i % 3) * DN_STAGE;
        const __half* As = (const __half*)buf;
        const __half* Bs = (const __half*)(buf + DN_B_OFF);
#pragma unroll
        for (int ks = 0; ks < 2; ks++) {
            int ko = ks * 16 + 2 * t4;
            uint32_t a[4][4];
#pragma unroll
            for (int mt = 0; mt < 4; mt++) {
                const __half* r0p = As + (mbase + mt * 16 + g) * KSTR + ko;
                const __half* r1p = r0p + 8 * KSTR;
                a[mt][0] = *(const uint32_t*)(r0p);
                a[mt][1] = *(const uint32_t*)(r1p);
                a[mt][2] = *(const uint32_t*)(r0p + 8);
                a[mt][3] = *(const uint32_t*)(r1p + 8);
            }
#pragma unroll
            for (int q = 0; q < 4; q++) {
                const __half* bn = Bs + (nbase + q * 8 + g) * KSTR + ko;
                uint32_t b0 = *(const uint32_t*)(bn);
                uint32_t b1 = *(const uint32_t*)(bn + 8);
#pragma unroll
                for (int mt = 0; mt < 4; mt++) mma16(c[mt][q], a[mt], b0, b1);
            }
        }
        CP_WAIT1();
        __syncthreads();
    }

    // epilogue: out[tok] += w * o (2 commutative adds/element -> deterministic)
#pragma unroll
    for (int mt = 0; mt < 4; mt++) {
        int r0 = mbase + mt * 16 + g;
#pragma unroll
        for (int nq = 0; nq < 4; nq++) {
            size_t col = (size_t)ntile * 128 + nbase + nq * 8 + t4 * 2;
            int e0 = s_ent[r0];
            if (e0 >= 0) {
                float w = s_w[r0];
                float* o = out + (size_t)(e0 >> 1) * D_DIM + col;
                atomicAdd(o,     c[mt][nq][0] * w);
                atomicAdd(o + 1, c[mt][nq][1] * w);
            }
            int e1 = s_ent[r0 + 8];
            if (e1 >= 0) {
                float w = s_w[r0 + 8];
                float* o = out + (size_t)(e1 >> 1) * D_DIM + col;
                atomicAdd(o,     c[mt][nq][2] * w);
                atomicAdd(o + 1, c[mt][nq][3] * w);
            }
        }
    }
}

// ---------------- launcher ----------------
extern "C" void kernel_launch(void* const* d_in, const int* in_sizes, int n_in,
                              void* d_out, int out_size) {
    const float* x   = (const float*)d_in[0];
    const float* gw  = (const float*)d_in[1];
    const float* wi0 = (const float*)d_in[2];
    const float* wi1 = (const float*)d_in[3];
    const float* wo  = (const float*)d_in[4];
    float* out = (float*)d_out;

    cudaFuncSetAttribute(ffn_up_kernel, cudaFuncAttributeMaxDynamicSharedMemorySize, UP_SMEM);
    cudaFuncSetAttribute(ffn_dn_kernel, cudaFuncAttributeMaxDynamicSharedMemorySize, DN_SMEM);

    __half* wi0t; cudaGetSymbolAddress((void**)&wi0t, g_wi0t);
    __half* wi1t; cudaGetSymbolAddress((void**)&wi1t, g_wi1t);
    __half* wot;  cudaGetSymbolAddress((void**)&wot,  g_wot);

    zero_init_kernel<<<(T_TOK * D_DIM / 4) / 256, 256>>>(out);

    dim3 tb(32, 8);
    dim3 tg_i(F_DIM / 32, D_DIM / 32, E_NUM);   // wi*: src [D][F] -> dst [F][D]
    transpose_fp16_kernel<<<tg_i, tb>>>(wi0, wi0t, D_DIM, F_DIM);
    transpose_fp16_kernel<<<tg_i, tb>>>(wi1, wi1t, D_DIM, F_DIM);
    dim3 tg_o(D_DIM / 32, F_DIM / 32, E_NUM);   // wo: src [F][D] -> dst [D][F]
    transpose_fp16_kernel<<<tg_o, tb>>>(wo, wot, F_DIM, D_DIM);

    router_kernel<<<T_TOK / 8, 256>>>(x, gw);

    dim3 gup(F_DIM / 64, T_TOK / BM, E_NUM);    // (64, 64, 8)
    ffn_up_kernel<<<gup, 256, UP_SMEM>>>();

    dim3 gdn(D_DIM / 128, T_TOK / BM, E_NUM);   // (8, 64, 8)
    ffn_dn_kernel<<<gdn, 256, DN_SMEM>>>(out);
}